// round 15
// baseline (speedup 1.0000x reference)
#include <cuda_runtime.h>
#include <cuda_bf16.h>
#include <mma.h>
#include <math.h>
#include <stdint.h>
#define DEV_INLINE __device__ __forceinline__
typedef __nv_bfloat16 bf16;
using namespace nvcuda;

constexpr int BB=8, NTOK=1024, IND=2048, DIM=512, NH=8, DHD=64, DEPTH=2, NE=4, NC=10;
constexpr int SEQ=NTOK+1, BS=BB*SEQ, M0=BB*NTOK, QD=3*DIM, KTP=1040;
constexpr long TSZ=(long)BS*DIM, QKVSZ=(long)BS*QD, SS=(long)SEQ*SEQ;
constexpr int NSLICE=NE*BB*NH;

__device__ float g_R[(size_t)M0*DIM];
__device__ float g_rmean[BB*DIM];
__device__ float g_gsoft[BB*NE];
__device__ float g_t[(size_t)NE*TSZ];
__device__ float g_h[(size_t)NE*TSZ];
__device__ float g_qkv[(size_t)NE*QKVSZ];
__device__ float g_sc[(size_t)NSLICE*SS];
__device__ float g_kt[(size_t)NSLICE*DHD*KTP];
__device__ float g_ao[(size_t)NE*TSZ];
__device__ float g_u[(size_t)NE*TSZ];
__device__ float g_late[NE*BB*DIM];
__device__ float g_loge[NE*BB*NC];

DEV_INLINE float gelu_f(float x){return 0.5f*x*(1.f+tanhf(0.7978845608028654f*(x+0.044715f*x*x*x)));}
DEV_INLINE float brsum(float v,float*sm){
    #pragma unroll
    for(int o=16;o;o>>=1)v+=__shfl_xor_sync(0xffffffffu,v,o);
    int t=threadIdx.x;if((t&31)==0)sm[t>>5]=v;__syncthreads();
    if(t<32){float z=(t<(int)(blockDim.x>>5))?sm[t]:0.f;
        #pragma unroll
        for(int o=4;o;o>>=1)z+=__shfl_xor_sync(0xffffffffu,z,o);
        if(t==0)sm[0]=z;}
    __syncthreads();float r=sm[0];__syncthreads();return r;}
DEV_INLINE float brmax(float v,float*sm){
    #pragma unroll
    for(int o=16;o;o>>=1)v=fmaxf(v,__shfl_xor_sync(0xffffffffu,v,o));
    int t=threadIdx.x;if((t&31)==0)sm[t>>5]=v;__syncthreads();
    if(t<32){float z=(t<(int)(blockDim.x>>5))?sm[t]:-1e30f;
        #pragma unroll
        for(int o=4;o;o>>=1)z=fmaxf(z,__shfl_xor_sync(0xffffffffu,z,o));
        if(t==0)sm[0]=z;}
    __syncthreads();float r=sm[0];__syncthreads();return r;}

// ======== VALIDATED wmma split-bf16 GEMM (g_wdiag pattern + guards) ========
// C[M,N] = act(alpha*A[M,K](fp32)@B[K,N](fp32) + bias + res). res may alias C.
template<int BN,int ACT,bool BIAS,bool RES,bool SHIFT>
DEV_INLINE void wmma_gemm(const float* __restrict__ A,long lda,
                          const float* __restrict__ B,long ldb,
                          const float* __restrict__ bias,const float* res,long ldres,
                          float* C,long ldc,int M,int N,int K,float alpha){
    constexpr int STRA=24, STRB=BN+8, NT=BN/16;
    __shared__ __align__(32) bf16 sAh[128*STRA], sAl[128*STRA];
    __shared__ __align__(32) bf16 sBh[16*STRB], sBl[16*STRB];
    __shared__ __align__(32) float stg[8][256];
    const int tid=threadIdx.x, w=tid>>5, l=tid&31;
    const int row0=blockIdx.y*128, col0=blockIdx.x*BN;

    wmma::fragment<wmma::accumulator,16,16,16,float> acc[NT];
    #pragma unroll
    for(int nt=0;nt<NT;nt++) wmma::fill_fragment(acc[nt],0.f);

    for(int kt=0;kt<K;kt+=16){
        for(int i=tid;i<128*16;i+=256){
            int r=i>>4,k=i&15;
            int gr=row0+r, gk=kt+k;
            float v=(gr<M&&gk<K)?A[(long)gr*lda+gk]:0.f;
            bf16 hh=__float2bfloat16(v);
            sAh[r*STRA+k]=hh;
            sAl[r*STRA+k]=__float2bfloat16(v-__bfloat162float(hh));
        }
        for(int i=tid;i<16*BN;i+=256){
            int k=i/BN,n=i-k*BN;
            int gk=kt+k, gc=col0+n;
            float v=(gk<K&&gc<N)?B[(long)gk*ldb+gc]:0.f;
            bf16 hh=__float2bfloat16(v);
            sBh[k*STRB+n]=hh;
            sBl[k*STRB+n]=__float2bfloat16(v-__bfloat162float(hh));
        }
        __syncthreads();
        wmma::fragment<wmma::matrix_a,16,16,16,bf16,wmma::row_major> fah,fal;
        wmma::load_matrix_sync(fah,&sAh[w*16*STRA],STRA);
        wmma::load_matrix_sync(fal,&sAl[w*16*STRA],STRA);
        #pragma unroll
        for(int nt=0;nt<NT;nt++){
            wmma::fragment<wmma::matrix_b,16,16,16,bf16,wmma::row_major> fbh,fbl;
            wmma::load_matrix_sync(fbh,&sBh[nt*16],STRB);
            wmma::load_matrix_sync(fbl,&sBl[nt*16],STRB);
            wmma::mma_sync(acc[nt],fah,fbh,acc[nt]);
            wmma::mma_sync(acc[nt],fah,fbl,acc[nt]);
            wmma::mma_sync(acc[nt],fal,fbh,acc[nt]);
        }
        __syncthreads();
    }
    #pragma unroll
    for(int nt=0;nt<NT;nt++){
        wmma::store_matrix_sync(stg[w],acc[nt],16,wmma::mem_row_major);
        __syncwarp();
        int rr=l>>1, c0=(l&1)*8;
        int r=row0+w*16+rr;
        if(r<M){
            long orow=SHIFT?((long)r+r/1024+1):(long)r;
            #pragma unroll
            for(int j=0;j<8;j++){
                int cc=col0+nt*16+c0+j;
                if(cc>=N) continue;
                float v=stg[w][rr*16+c0+j]*alpha;
                if(BIAS)v+=bias[cc];
                if(RES)v+=res[orow*ldres+cc];
                if(ACT==1)v=fmaxf(v,0.f);else if(ACT==2)v=gelu_f(v);
                C[orow*ldc+cc]=v;
            }
        }
        __syncwarp();
    }
}

// ---------------- GEMM wrapper kernels ----------------
__global__ void __launch_bounds__(256) wg_router(const float*x,const float*Wr,const float*br){
    wmma_gemm<128,1,true,false,false>(x,IND,Wr,DIM,br,nullptr,0,g_R,DIM,M0,DIM,IND,1.f);}
__global__ void __launch_bounds__(256) wg_expert(const float*x,const float*Wp,const float*bp){
    long e=blockIdx.z;
    wmma_gemm<128,1,true,false,true>(x,IND,Wp+e*IND*DIM,DIM,bp+e*DIM,nullptr,0,
        g_t+e*TSZ,DIM,M0,DIM,IND,1.f);}
__global__ void __launch_bounds__(256) wg_qkv(const float*Wqkv,const float*bqkv,int lyr){
    long e=blockIdx.z, we=e*DEPTH+lyr;
    wmma_gemm<128,0,true,false,false>(g_h+e*TSZ,DIM,Wqkv+we*DIM*QD,QD,bqkv+we*QD,nullptr,0,
        g_qkv+e*QKVSZ,QD,BS,QD,DIM,1.f);}
__global__ void __launch_bounds__(256) wg_scores(){
    long z=blockIdx.z;
    long e=z/(BB*NH), b=(z/NH)%BB, h=z%NH;
    const float* q=g_qkv+e*QKVSZ+b*(long)SEQ*QD+h*DHD;
    wmma_gemm<128,0,false,false,false>(q,QD,g_kt+(size_t)z*DHD*KTP,KTP,nullptr,nullptr,0,
        g_sc+(size_t)z*SS,SEQ,SEQ,SEQ,DHD,0.125f);}
__global__ void __launch_bounds__(256) wg_av(){
    long z=blockIdx.z;
    long e=z/(BB*NH), b=(z/NH)%BB, h=z%NH;
    wmma_gemm<64,0,false,false,false>(g_sc+(size_t)z*SS,SEQ,
        g_qkv+e*QKVSZ+b*(long)SEQ*QD+2*DIM+h*DHD,QD,nullptr,nullptr,0,
        g_ao+e*TSZ+b*(long)SEQ*DIM+h*DHD,DIM,SEQ,DHD,SEQ,1.f);}
__global__ void __launch_bounds__(256) wg_oproj(const float*Wo,const float*bo,int lyr){
    long e=blockIdx.z, we=e*DEPTH+lyr;
    wmma_gemm<128,0,true,true,false>(g_ao+e*TSZ,DIM,Wo+we*DIM*DIM,DIM,bo+we*DIM,
        g_t+e*TSZ,DIM,g_t+e*TSZ,DIM,BS,DIM,DIM,1.f);}
__global__ void __launch_bounds__(256) wg_mlp1(const float*W1,const float*b1,int lyr){
    long e=blockIdx.z, we=e*DEPTH+lyr;
    wmma_gemm<128,2,true,false,false>(g_h+e*TSZ,DIM,W1+we*DIM*DIM,DIM,b1+we*DIM,nullptr,0,
        g_u+e*TSZ,DIM,BS,DIM,DIM,1.f);}
__global__ void __launch_bounds__(256) wg_mlp2(const float*W2,const float*b2,int lyr){
    long e=blockIdx.z, we=e*DEPTH+lyr;
    wmma_gemm<128,0,true,true,false>(g_u+e*TSZ,DIM,W2+we*DIM*DIM,DIM,b2+we*DIM,
        g_t+e*TSZ,DIM,g_t+e*TSZ,DIM,BS,DIM,DIM,1.f);}

// K transpose: [SEQ,64] (stride QD) -> g_kt [64,KTP] per slice, zero-padded
__global__ void __launch_bounds__(256) k_kt(){
    __shared__ float t[32][33];
    long z=blockIdx.z;
    long e=z/(BB*NH), b=(z/NH)%BB, h=z%NH;
    const float* src=g_qkv+e*QKVSZ+b*(long)SEQ*QD+DIM+h*DHD;
    int s0=blockIdx.x*32, d0=blockIdx.y*32;
    int tx=threadIdx.x&31, ty=threadIdx.x>>5;
    for(int i=ty;i<32;i+=8){
        int s=s0+i;
        t[i][tx]=(s<SEQ)?src[(long)s*QD+d0+tx]:0.f;
    }
    __syncthreads();
    float* dst=g_kt+(size_t)z*DHD*KTP;
    for(int i=ty;i<32;i+=8){
        int d=d0+i, s=s0+tx;
        if(s<KTP) dst[(long)d*KTP+s]=t[tx][i];
    }
}

// ---------------- non-GEMM kernels (proven) ----------------
__global__ void __launch_bounds__(512) k_set_cls(const float*cls){
    int b=blockIdx.x,e=blockIdx.y;
    g_t[(size_t)e*TSZ+(size_t)b*SEQ*DIM+threadIdx.x]=cls[e*DIM+threadIdx.x];}
__global__ void __launch_bounds__(256) k_ln(const float*g,const float*bb,long gE,int fin){
    __shared__ float sm[8];
    int e=blockIdx.y;const float*xp;float*op;
    if(fin==0){long row=blockIdx.x;xp=g_t+(long)e*TSZ+row*DIM;op=g_h+(long)e*TSZ+row*DIM;}
    else{int b=blockIdx.x;xp=g_t+(long)e*TSZ+(long)b*SEQ*DIM;op=g_late+((long)e*BB+b)*DIM;}
    const float*gp=g+e*gE;const float*bp=bb+e*gE;
    int t=threadIdx.x;
    float x0=xp[t],x1=xp[t+256];
    float s=brsum(x0+x1,sm), sq=brsum(x0*x0+x1*x1,sm);
    float m=s*(1.f/DIM), v=sq*(1.f/DIM)-m*m, inv=rsqrtf(v+1e-5f);
    op[t]=(x0-m)*inv*gp[t]+bp[t];
    op[t+256]=(x1-m)*inv*gp[t+256]+bp[t+256];}
__global__ void __launch_bounds__(256) k_softmax(){
    __shared__ float sm[8];
    int e=blockIdx.y;long row=blockIdx.x;
    float*p=g_sc+(long)e*((long)BB*NH*SS)+row*SEQ;
    int t=threadIdx.x;float v[5],mx=-1e30f;
    #pragma unroll
    for(int i=0;i<5;i++){int idx=t+i*256;v[i]=(idx<SEQ)?p[idx]:-1e30f;mx=fmaxf(mx,v[i]);}
    mx=brmax(mx,sm);
    float s=0.f;
    #pragma unroll
    for(int i=0;i<5;i++){int idx=t+i*256;if(idx<SEQ){v[i]=__expf(v[i]-mx);s+=v[i];}else v[i]=0.f;}
    s=brsum(s,sm);float inv=1.f/s;
    #pragma unroll
    for(int i=0;i<5;i++){int idx=t+i*256;if(idx<SEQ)p[idx]=v[i]*inv;}}
__global__ void __launch_bounds__(512) k_meanpool(){
    int b=blockIdx.x,d=threadIdx.x;
    const float*p=g_R+(long)b*NTOK*DIM+d;float s=0.f;
    for(int n=0;n<NTOK;n++)s+=p[(long)n*DIM];
    g_rmean[b*DIM+d]=s*(1.f/NTOK);}
__global__ void __launch_bounds__(32) k_router_head(const float*Wrf,const float*brf){
    __shared__ float lg[BB][NE];
    int t=threadIdx.x;
    if(t<BB*NE){int b=t/NE,e=t%NE;float s=brf[e];
        for(int d=0;d<DIM;d++)s+=g_rmean[b*DIM+d]*Wrf[d*NE+e];
        lg[b][e]=s;}
    __syncthreads();
    if(t<BB){float mx=-1e30f;
        for(int e=0;e<NE;e++)mx=fmaxf(mx,lg[t][e]);
        float ex[NE],sum=0.f;
        for(int e=0;e<NE;e++){ex[e]=__expf(lg[t][e]-mx);sum+=ex[e];}
        for(int e=0;e<NE;e++)g_gsoft[t*NE+e]=ex[e]/sum;}}
__global__ void __launch_bounds__(320) k_head(const float*Wh,const float*bh){
    int eb=blockIdx.x,e=eb/BB;
    int w=threadIdx.x>>5,lane=threadIdx.x&31;
    const float*lat=g_late+(long)eb*DIM;const float*wp=Wh+(long)e*DIM*NC;
    float s=0.f;
    for(int d=lane;d<DIM;d+=32)s+=lat[d]*wp[d*NC+w];
    #pragma unroll
    for(int o=16;o;o>>=1)s+=__shfl_xor_sync(0xffffffffu,s,o);
    if(lane==0)g_loge[eb*NC+w]=s+bh[e*NC+w];}
__global__ void __launch_bounds__(256) k_combine(float*out,int n){
    int idx=blockIdx.x*256+threadIdx.x;if(idx>=n)return;
    if(idx<BB*DIM){int b=idx/DIM,d=idx%DIM;float s=0.f;
        for(int e=0;e<NE;e++)s+=g_gsoft[b*NE+e]*g_late[(e*BB+b)*DIM+d];out[idx]=s;}
    else if(idx<BB*DIM+BB*NC){int i=idx-BB*DIM,b=i/NC,c=i%NC;float s=0.f;
        for(int e=0;e<NE;e++)s+=g_gsoft[b*NE+e]*g_loge[(e*BB+b)*NC+c];out[idx]=s;}
    else if(idx<BB*DIM+BB*NC+BB*NE)out[idx]=g_gsoft[idx-BB*DIM-BB*NC];
    else out[idx]=0.f;}

extern "C" void kernel_launch(void* const* d_in,const int* in_sizes,int n_in,void* d_out,int out_size){
    const float*x=(const float*)d_in[0],*Wr=(const float*)d_in[1],*br=(const float*)d_in[2];
    const float*Wrf=(const float*)d_in[3],*brf=(const float*)d_in[4];
    const float*Wp=(const float*)d_in[5],*bp=(const float*)d_in[6],*cls=(const float*)d_in[7];
    const float*ln1g=(const float*)d_in[8],*ln1b=(const float*)d_in[9];
    const float*Wqkv=(const float*)d_in[10],*bqkv=(const float*)d_in[11];
    const float*Wo=(const float*)d_in[12],*bo=(const float*)d_in[13];
    const float*ln2g=(const float*)d_in[14],*ln2b=(const float*)d_in[15];
    const float*W1=(const float*)d_in[16],*b1=(const float*)d_in[17];
    const float*W2=(const float*)d_in[18],*b2=(const float*)d_in[19];
    const float*lnfg=(const float*)d_in[20],*lnfb=(const float*)d_in[21];
    const float*Wh=(const float*)d_in[22],*bh=(const float*)d_in[23];
    float*out=(float*)d_out;

    const int gyM0=M0/128;                 // 64
    const int gyBS=(BS+127)/128;           // 65
    const int gyS=(SEQ+127)/128;           // 9

    wg_router<<<dim3(DIM/128,gyM0),256>>>(x,Wr,br);
    k_meanpool<<<BB,DIM>>>();
    k_router_head<<<1,32>>>(Wrf,brf);

    wg_expert<<<dim3(DIM/128,gyM0,NE),256>>>(x,Wp,bp);
    k_set_cls<<<dim3(BB,NE),DIM>>>(cls);

    for(int l=0;l<DEPTH;l++){
        k_ln<<<dim3(BS,NE),256>>>(ln1g+l*DIM,ln1b+l*DIM,(long)DEPTH*DIM,0);
        wg_qkv<<<dim3(QD/128,gyBS,NE),256>>>(Wqkv,bqkv,l);
        k_kt<<<dim3((KTP+31)/32,DHD/32,NSLICE),256>>>();
        wg_scores<<<dim3(gyS,gyS,NSLICE),256>>>();
        k_softmax<<<dim3(BB*NH*SEQ,NE),256>>>();
        wg_av<<<dim3(1,gyS,NSLICE),256>>>();
        wg_oproj<<<dim3(DIM/128,gyBS,NE),256>>>(Wo,bo,l);
        k_ln<<<dim3(BS,NE),256>>>(ln2g+l*DIM,ln2b+l*DIM,(long)DEPTH*DIM,0);
        wg_mlp1<<<dim3(DIM/128,gyBS,NE),256>>>(W1,b1,l);
        wg_mlp2<<<dim3(DIM/128,gyBS,NE),256>>>(W2,b2,l);
    }
    k_ln<<<dim3(BB,NE),256>>>(lnfg,lnfb,(long)DIM,1);
    k_head<<<NE*BB,320>>>(Wh,bh);
    k_combine<<<(out_size+255)/256,256>>>(out,out_size);
}

// round 16
// speedup vs baseline: 1.4395x; 1.4395x over previous
#include <cuda_runtime.h>
#include <cuda_bf16.h>
#include <mma.h>
#include <math.h>
#include <stdint.h>
#define DEV_INLINE __device__ __forceinline__
typedef __nv_bfloat16 bf16;
using namespace nvcuda;

constexpr int BB=8, NTOK=1024, IND=2048, DIM=512, NH=8, DHD=64, DEPTH=2, NE=4, NC=10;
constexpr int SEQ=NTOK+1, BS=BB*SEQ, M0=BB*NTOK, QD=3*DIM;
constexpr int KTP=1040, PLD=1056;
constexpr long TSZ=(long)BS*DIM, QKVSZ=(long)BS*QD, SS=(long)SEQ*SEQ;
constexpr int NSLICE=NE*BB*NH;

// fp32 state
__device__ float g_R[(size_t)M0*DIM];
__device__ float g_rmean[BB*DIM];
__device__ float g_gsoft[BB*NE];
__device__ float g_t[(size_t)NE*TSZ];
__device__ float g_sc[(size_t)NSLICE*SS];
__device__ float g_late[NE*BB*DIM];
__device__ float g_loge[NE*BB*NC];
// split-bf16 state
__device__ bf16 g_xh[(size_t)M0*IND], g_xl[(size_t)M0*IND];
__device__ bf16 g_hh[(size_t)NE*TSZ], g_hl[(size_t)NE*TSZ];
__device__ bf16 g_qvh[(size_t)NE*QKVSZ], g_qvl[(size_t)NE*QKVSZ];
__device__ bf16 g_kth[(size_t)NSLICE*DHD*KTP], g_ktl[(size_t)NSLICE*DHD*KTP];
__device__ bf16 g_ph[(size_t)NSLICE*SEQ*PLD], g_pl[(size_t)NSLICE*SEQ*PLD];
__device__ bf16 g_aoh[(size_t)NE*TSZ], g_aol[(size_t)NE*TSZ];
__device__ bf16 g_uh[(size_t)NE*TSZ], g_ul[(size_t)NE*TSZ];
// split weights (natural [K,N] layout, no transpose)
__device__ bf16 g_wrh[(size_t)IND*DIM], g_wrl[(size_t)IND*DIM];
__device__ bf16 g_wph[(size_t)NE*IND*DIM], g_wpl[(size_t)NE*IND*DIM];
__device__ bf16 g_wqh[(size_t)NE*DEPTH*DIM*QD], g_wql[(size_t)NE*DEPTH*DIM*QD];
__device__ bf16 g_woh[(size_t)NE*DEPTH*DIM*DIM], g_wol[(size_t)NE*DEPTH*DIM*DIM];
__device__ bf16 g_w1h[(size_t)NE*DEPTH*DIM*DIM], g_w1l[(size_t)NE*DEPTH*DIM*DIM];
__device__ bf16 g_w2h[(size_t)NE*DEPTH*DIM*DIM], g_w2l[(size_t)NE*DEPTH*DIM*DIM];

DEV_INLINE float gelu_f(float x){return 0.5f*x*(1.f+tanhf(0.7978845608028654f*(x+0.044715f*x*x*x)));}
DEV_INLINE void split2(float v,bf16&h,bf16&l){h=__float2bfloat16(v);l=__float2bfloat16(v-__bfloat162float(h));}
DEV_INLINE float brsum(float v,float*sm){
    #pragma unroll
    for(int o=16;o;o>>=1)v+=__shfl_xor_sync(0xffffffffu,v,o);
    int t=threadIdx.x;if((t&31)==0)sm[t>>5]=v;__syncthreads();
    if(t<32){float z=(t<(int)(blockDim.x>>5))?sm[t]:0.f;
        #pragma unroll
        for(int o=4;o;o>>=1)z+=__shfl_xor_sync(0xffffffffu,z,o);
        if(t==0)sm[0]=z;}
    __syncthreads();float r=sm[0];__syncthreads();return r;}
DEV_INLINE float brmax(float v,float*sm){
    #pragma unroll
    for(int o=16;o;o>>=1)v=fmaxf(v,__shfl_xor_sync(0xffffffffu,v,o));
    int t=threadIdx.x;if((t&31)==0)sm[t>>5]=v;__syncthreads();
    if(t<32){float z=(t<(int)(blockDim.x>>5))?sm[t]:-1e30f;
        #pragma unroll
        for(int o=4;o;o>>=1)z=fmaxf(z,__shfl_xor_sync(0xffffffffu,z,o));
        if(t==0)sm[0]=z;}
    __syncthreads();float r=sm[0];__syncthreads();return r;}

// ======== wmma split-bf16 GEMM v2: pre-split bf16 inputs, BK=32, warp 32x(BN/2) ========
// C = act(alpha*(Ah+Al)[M,K]@ (Bh+Bl)[K,N] + bias + res). res may alias C.
// Requirements: K loop bound mult of 32; A rows padded/readable to K; B rows guarded by Kb;
// B cols readable up to Ncap (mult of 8). lda/ldb mult of 8, 16B-aligned bases.
template<int BN,int ACT,bool BIAS,bool RES,bool SHIFT,bool OUTSPLIT>
DEV_INLINE void tc2(const bf16* __restrict__ Ah,const bf16* __restrict__ Al,long lda,
                    const bf16* __restrict__ Bh,const bf16* __restrict__ Bl,long ldb,
                    const float* __restrict__ bias,const float* res,long ldres,
                    float* Cf,bf16* Ch,bf16* Cl,long ldc,
                    int M,int N,int K,int Kb,int Ncap,float alpha){
    constexpr int STRA=40, STRB=BN+8, NTW=BN/32, WCOL=BN/2;
    __shared__ __align__(32) bf16 sAh[128*STRA], sAl[128*STRA];
    __shared__ __align__(32) bf16 sBh[32*STRB], sBl[32*STRB];
    __shared__ __align__(32) float stg[8][256];
    const int tid=threadIdx.x, w=tid>>5, l=tid&31;
    const int wm=w&3, wn=w>>2;
    const int row0=blockIdx.y*128, col0=blockIdx.x*BN;
    const uint4 z4=make_uint4(0u,0u,0u,0u);

    wmma::fragment<wmma::accumulator,16,16,16,float> acc[2][NTW];
    #pragma unroll
    for(int mt=0;mt<2;mt++)
        #pragma unroll
        for(int nt=0;nt<NTW;nt++) wmma::fill_fragment(acc[mt][nt],0.f);

    for(int kt=0;kt<K;kt+=32){
        // A tile 128x32 (h and l)
        #pragma unroll
        for(int q=0;q<2;q++){
            int u=tid+q*256;
            int r=u>>2, cb=(u&3)*8;
            int gr=row0+r;
            uint4 vh=z4, vl=z4;
            if(gr<M){
                vh=*(const uint4*)(Ah+(long)gr*lda+kt+cb);
                vl=*(const uint4*)(Al+(long)gr*lda+kt+cb);
            }
            *(uint4*)(sAh+r*STRA+cb)=vh;
            *(uint4*)(sAl+r*STRA+cb)=vl;
        }
        // B tile 32xBN
        constexpr int UN=32*BN/8;
        for(int u=tid;u<UN;u+=256){
            int r=u/(BN/8), cb=(u%(BN/8))*8;
            int gk=kt+r;
            uint4 vh=z4, vl=z4;
            if(gk<Kb && col0+cb+8<=Ncap){
                vh=*(const uint4*)(Bh+(long)gk*ldb+col0+cb);
                vl=*(const uint4*)(Bl+(long)gk*ldb+col0+cb);
            }
            *(uint4*)(sBh+r*STRB+cb)=vh;
            *(uint4*)(sBl+r*STRB+cb)=vl;
        }
        __syncthreads();
        #pragma unroll
        for(int ks=0;ks<2;ks++){
            wmma::fragment<wmma::matrix_b,16,16,16,bf16,wmma::row_major> fbh[NTW],fbl[NTW];
            #pragma unroll
            for(int nt=0;nt<NTW;nt++){
                wmma::load_matrix_sync(fbh[nt],&sBh[(ks*16)*STRB+wn*WCOL+nt*16],STRB);
                wmma::load_matrix_sync(fbl[nt],&sBl[(ks*16)*STRB+wn*WCOL+nt*16],STRB);
            }
            #pragma unroll
            for(int mt=0;mt<2;mt++){
                wmma::fragment<wmma::matrix_a,16,16,16,bf16,wmma::row_major> fah,fal;
                wmma::load_matrix_sync(fah,&sAh[(wm*32+mt*16)*STRA+ks*16],STRA);
                wmma::load_matrix_sync(fal,&sAl[(wm*32+mt*16)*STRA+ks*16],STRA);
                #pragma unroll
                for(int nt=0;nt<NTW;nt++){
                    wmma::mma_sync(acc[mt][nt],fah,fbh[nt],acc[mt][nt]);
                    wmma::mma_sync(acc[mt][nt],fah,fbl[nt],acc[mt][nt]);
                    wmma::mma_sync(acc[mt][nt],fal,fbh[nt],acc[mt][nt]);
                }
            }
        }
        __syncthreads();
    }
    #pragma unroll
    for(int mt=0;mt<2;mt++){
        #pragma unroll
        for(int nt=0;nt<NTW;nt++){
            wmma::store_matrix_sync(stg[w],acc[mt][nt],16,wmma::mem_row_major);
            __syncwarp();
            int rr=l>>1, c0=(l&1)*8;
            int r=row0+wm*32+mt*16+rr;
            if(r<M){
                long orow=SHIFT?((long)r+r/1024+1):(long)r;
                #pragma unroll
                for(int j=0;j<8;j++){
                    int cc=col0+wn*WCOL+nt*16+c0+j;
                    if(cc>=N) continue;
                    float v=stg[w][rr*16+c0+j]*alpha;
                    if(BIAS)v+=bias[cc];
                    if(RES)v+=res[orow*ldres+cc];
                    if(ACT==1)v=fmaxf(v,0.f);else if(ACT==2)v=gelu_f(v);
                    if(OUTSPLIT){bf16 hh,ll;split2(v,hh,ll);Ch[orow*ldc+cc]=hh;Cl[orow*ldc+cc]=ll;}
                    else Cf[orow*ldc+cc]=v;
                }
            }
            __syncwarp();
        }
    }
}

// ---------------- GEMM wrappers (globals referenced in device code) ----------------
__global__ void __launch_bounds__(256) wg_router(const float*br){
    tc2<128,1,true,false,false,false>(g_xh,g_xl,IND,g_wrh,g_wrl,DIM,br,nullptr,0,
        g_R,nullptr,nullptr,DIM,M0,DIM,IND,IND,DIM,1.f);}
__global__ void __launch_bounds__(256) wg_expert(const float*bp){
    long e=blockIdx.z;
    tc2<128,1,true,false,true,false>(g_xh,g_xl,IND,g_wph+e*IND*DIM,g_wpl+e*IND*DIM,DIM,
        bp+e*DIM,nullptr,0,g_t+e*TSZ,nullptr,nullptr,DIM,M0,DIM,IND,IND,DIM,1.f);}
__global__ void __launch_bounds__(256) wg_qkv(const float*bqkv,int lyr){
    long e=blockIdx.z, we=e*DEPTH+lyr;
    tc2<128,0,true,false,false,true>(g_hh+e*TSZ,g_hl+e*TSZ,DIM,
        g_wqh+we*DIM*QD,g_wql+we*DIM*QD,QD,bqkv+we*QD,nullptr,0,
        nullptr,g_qvh+e*QKVSZ,g_qvl+e*QKVSZ,QD,BS,QD,DIM,DIM,QD,1.f);}
__global__ void __launch_bounds__(256) wg_scores(){
    long z=blockIdx.z;
    long e=z/(BB*NH), b=(z/NH)%BB, h=z%NH;
    const bf16* qh=g_qvh+e*QKVSZ+b*(long)SEQ*QD+h*DHD;
    const bf16* ql=g_qvl+e*QKVSZ+b*(long)SEQ*QD+h*DHD;
    tc2<128,0,false,false,false,false>(qh,ql,QD,
        g_kth+(size_t)z*DHD*KTP,g_ktl+(size_t)z*DHD*KTP,KTP,nullptr,nullptr,0,
        g_sc+(size_t)z*SS,nullptr,nullptr,SEQ,SEQ,SEQ,DHD,DHD,KTP,0.125f);}
__global__ void __launch_bounds__(256) wg_av(){
    long z=blockIdx.z;
    long e=z/(BB*NH), b=(z/NH)%BB, h=z%NH;
    tc2<64,0,false,false,false,true>(
        g_ph+(size_t)z*SEQ*PLD,g_pl+(size_t)z*SEQ*PLD,PLD,
        g_qvh+e*QKVSZ+b*(long)SEQ*QD+2*DIM+h*DHD,g_qvl+e*QKVSZ+b*(long)SEQ*QD+2*DIM+h*DHD,QD,
        nullptr,nullptr,0,
        nullptr,g_aoh+e*TSZ+b*(long)SEQ*DIM+h*DHD,g_aol+e*TSZ+b*(long)SEQ*DIM+h*DHD,DIM,
        SEQ,DHD,PLD,SEQ,DHD,1.f);}
__global__ void __launch_bounds__(256) wg_oproj(const float*bo,int lyr){
    long e=blockIdx.z, we=e*DEPTH+lyr;
    tc2<128,0,true,true,false,false>(g_aoh+e*TSZ,g_aol+e*TSZ,DIM,
        g_woh+we*DIM*DIM,g_wol+we*DIM*DIM,DIM,bo+we*DIM,g_t+e*TSZ,DIM,
        g_t+e*TSZ,nullptr,nullptr,DIM,BS,DIM,DIM,DIM,DIM,1.f);}
__global__ void __launch_bounds__(256) wg_mlp1(const float*b1,int lyr){
    long e=blockIdx.z, we=e*DEPTH+lyr;
    tc2<128,2,true,false,false,true>(g_hh+e*TSZ,g_hl+e*TSZ,DIM,
        g_w1h+we*DIM*DIM,g_w1l+we*DIM*DIM,DIM,b1+we*DIM,nullptr,0,
        nullptr,g_uh+e*TSZ,g_ul+e*TSZ,DIM,BS,DIM,DIM,DIM,DIM,1.f);}
__global__ void __launch_bounds__(256) wg_mlp2(const float*b2,int lyr){
    long e=blockIdx.z, we=e*DEPTH+lyr;
    tc2<128,0,true,true,false,false>(g_uh+e*TSZ,g_ul+e*TSZ,DIM,
        g_w2h+we*DIM*DIM,g_w2l+we*DIM*DIM,DIM,b2+we*DIM,g_t+e*TSZ,DIM,
        g_t+e*TSZ,nullptr,nullptr,DIM,BS,DIM,DIM,DIM,DIM,1.f);}

// ---------------- prep / elementwise ----------------
__global__ void __launch_bounds__(256) k_split(const float* __restrict__ s,bf16* __restrict__ h,
                                               bf16* __restrict__ l,long n){
    for(long i=blockIdx.x*256L+threadIdx.x;i<n;i+=(long)gridDim.x*256L){
        float v=s[i];bf16 hh=__float2bfloat16(v);h[i]=hh;l[i]=__float2bfloat16(v-__bfloat162float(hh));}}
// K^T: per slice z, src bf16 [SEQ,64] (stride QD) -> dst [64,KTP], zero-padded cols
__global__ void __launch_bounds__(256) k_kt(){
    __shared__ bf16 th[32][33], tl[32][33];
    long z=blockIdx.z;
    long e=z/(BB*NH), b=(z/NH)%BB, h=z%NH;
    const bf16* sh=g_qvh+e*QKVSZ+b*(long)SEQ*QD+DIM+h*DHD;
    const bf16* sl=g_qvl+e*QKVSZ+b*(long)SEQ*QD+DIM+h*DHD;
    int s0=blockIdx.x*32, d0=blockIdx.y*32;
    int tx=threadIdx.x&31, ty=threadIdx.x>>5;
    for(int i=ty;i<32;i+=8){
        int s=s0+i;
        th[i][tx]=(s<SEQ)?sh[(long)s*QD+d0+tx]:bf16(0.f);
        tl[i][tx]=(s<SEQ)?sl[(long)s*QD+d0+tx]:bf16(0.f);
    }
    __syncthreads();
    bf16* dh=g_kth+(size_t)z*DHD*KTP;
    bf16* dl=g_ktl+(size_t)z*DHD*KTP;
    for(int i=ty;i<32;i+=8){
        int d=d0+i, s=s0+tx;
        if(s<KTP){ dh[(long)d*KTP+s]=th[tx][i]; dl[(long)d*KTP+s]=tl[tx][i]; }
    }
}
__global__ void __launch_bounds__(512) k_set_cls(const float*cls){
    int b=blockIdx.x,e=blockIdx.y;
    g_t[(size_t)e*TSZ+(size_t)b*SEQ*DIM+threadIdx.x]=cls[e*DIM+threadIdx.x];}
__global__ void __launch_bounds__(256) k_ln(const float*g,const float*bb,long gE,int fin){
    __shared__ float sm[8];
    int e=blockIdx.y;const float*xp;long ob;
    if(fin==0){long row=blockIdx.x;xp=g_t+(long)e*TSZ+row*DIM;ob=(long)e*TSZ+row*DIM;}
    else{int b=blockIdx.x;xp=g_t+(long)e*TSZ+(long)b*SEQ*DIM;ob=((long)e*BB+b)*DIM;}
    const float*gp=g+e*gE;const float*bp=bb+e*gE;
    int t=threadIdx.x;
    float x0=xp[t],x1=xp[t+256];
    float s=brsum(x0+x1,sm), sq=brsum(x0*x0+x1*x1,sm);
    float m=s*(1.f/DIM), v=sq*(1.f/DIM)-m*m, inv=rsqrtf(v+1e-5f);
    float y0=(x0-m)*inv*gp[t]+bp[t], y1=(x1-m)*inv*gp[t+256]+bp[t+256];
    if(fin==0){bf16 hh,ll;
        split2(y0,hh,ll);g_hh[ob+t]=hh;g_hl[ob+t]=ll;
        split2(y1,hh,ll);g_hh[ob+t+256]=hh;g_hl[ob+t+256]=ll;
    }else{g_late[ob+t]=y0;g_late[ob+t+256]=y1;}}
__global__ void __launch_bounds__(256) k_softmax(){
    __shared__ float sm[8];
    int e=blockIdx.y;long rowIn=blockIdx.x;
    const float*p=g_sc+(size_t)e*((long)BB*NH*SS)+rowIn*SEQ;
    long z=(long)e*(BB*NH)+rowIn/SEQ, q=rowIn%SEQ;
    bf16*oh=g_ph+(z*(long)SEQ+q)*PLD;
    bf16*ol=g_pl+(z*(long)SEQ+q)*PLD;
    int t=threadIdx.x;float v[5],mx=-1e30f;
    #pragma unroll
    for(int i=0;i<5;i++){int idx=t+i*256;v[i]=(idx<SEQ)?p[idx]:-1e30f;mx=fmaxf(mx,v[i]);}
    mx=brmax(mx,sm);
    float s=0.f;
    #pragma unroll
    for(int i=0;i<5;i++){int idx=t+i*256;if(idx<SEQ){v[i]=__expf(v[i]-mx);s+=v[i];}else v[i]=0.f;}
    s=brsum(s,sm);float inv=1.f/s;
    #pragma unroll
    for(int i=0;i<5;i++){
        int idx=t+i*256;
        if(idx<SEQ){bf16 hh,ll;split2(v[i]*inv,hh,ll);oh[idx]=hh;ol[idx]=ll;}
        else if(idx<PLD){oh[idx]=bf16(0.f);ol[idx]=bf16(0.f);}
    }}
__global__ void __launch_bounds__(512) k_meanpool(){
    int b=blockIdx.x,d=threadIdx.x;
    const float*p=g_R+(long)b*NTOK*DIM+d;float s=0.f;
    for(int n=0;n<NTOK;n++)s+=p[(long)n*DIM];
    g_rmean[b*DIM+d]=s*(1.f/NTOK);}
__global__ void __launch_bounds__(32) k_router_head(const float*Wrf,const float*brf){
    __shared__ float lg[BB][NE];
    int t=threadIdx.x;
    if(t<BB*NE){int b=t/NE,e=t%NE;float s=brf[e];
        for(int d=0;d<DIM;d++)s+=g_rmean[b*DIM+d]*Wrf[d*NE+e];
        lg[b][e]=s;}
    __syncthreads();
    if(t<BB){float mx=-1e30f;
        for(int e=0;e<NE;e++)mx=fmaxf(mx,lg[t][e]);
        float ex[NE],sum=0.f;
        for(int e=0;e<NE;e++){ex[e]=__expf(lg[t][e]-mx);sum+=ex[e];}
        for(int e=0;e<NE;e++)g_gsoft[t*NE+e]=ex[e]/sum;}}
__global__ void __launch_bounds__(320) k_head(const float*Wh,const float*bh){
    int eb=blockIdx.x,e=eb/BB;
    int w=threadIdx.x>>5,lane=threadIdx.x&31;
    const float*lat=g_late+(long)eb*DIM;const float*wp=Wh+(long)e*DIM*NC;
    float s=0.f;
    for(int d=lane;d<DIM;d+=32)s+=lat[d]*wp[d*NC+w];
    #pragma unroll
    for(int o=16;o;o>>=1)s+=__shfl_xor_sync(0xffffffffu,s,o);
    if(lane==0)g_loge[eb*NC+w]=s+bh[e*NC+w];}
__global__ void __launch_bounds__(256) k_combine(float*out,int n){
    int idx=blockIdx.x*256+threadIdx.x;if(idx>=n)return;
    if(idx<BB*DIM){int b=idx/DIM,d=idx%DIM;float s=0.f;
        for(int e=0;e<NE;e++)s+=g_gsoft[b*NE+e]*g_late[(e*BB+b)*DIM+d];out[idx]=s;}
    else if(idx<BB*DIM+BB*NC){int i=idx-BB*DIM,b=i/NC,c=i%NC;float s=0.f;
        for(int e=0;e<NE;e++)s+=g_gsoft[b*NE+e]*g_loge[(e*BB+b)*NC+c];out[idx]=s;}
    else if(idx<BB*DIM+BB*NC+BB*NE)out[idx]=g_gsoft[idx-BB*DIM-BB*NC];
    else out[idx]=0.f;}

extern "C" void kernel_launch(void* const* d_in,const int* in_sizes,int n_in,void* d_out,int out_size){
    const float*x=(const float*)d_in[0],*Wr=(const float*)d_in[1],*br=(const float*)d_in[2];
    const float*Wrf=(const float*)d_in[3],*brf=(const float*)d_in[4];
    const float*Wp=(const float*)d_in[5],*bp=(const float*)d_in[6],*cls=(const float*)d_in[7];
    const float*ln1g=(const float*)d_in[8],*ln1b=(const float*)d_in[9];
    const float*Wqkv=(const float*)d_in[10],*bqkv=(const float*)d_in[11];
    const float*Wo=(const float*)d_in[12],*bo=(const float*)d_in[13];
    const float*ln2g=(const float*)d_in[14],*ln2b=(const float*)d_in[15];
    const float*W1=(const float*)d_in[16],*b1=(const float*)d_in[17];
    const float*W2=(const float*)d_in[18],*b2=(const float*)d_in[19];
    const float*lnfg=(const float*)d_in[20],*lnfb=(const float*)d_in[21];
    const float*Wh=(const float*)d_in[22],*bh=(const float*)d_in[23];
    float*out=(float*)d_out;

    // true device addresses for split destinations
    void *xh,*xl,*wrh,*wrl,*wph,*wpl,*wqh,*wql,*woh,*wol,*w1h,*w1l,*w2h,*w2l;
    cudaGetSymbolAddress(&xh,g_xh);   cudaGetSymbolAddress(&xl,g_xl);
    cudaGetSymbolAddress(&wrh,g_wrh); cudaGetSymbolAddress(&wrl,g_wrl);
    cudaGetSymbolAddress(&wph,g_wph); cudaGetSymbolAddress(&wpl,g_wpl);
    cudaGetSymbolAddress(&wqh,g_wqh); cudaGetSymbolAddress(&wql,g_wql);
    cudaGetSymbolAddress(&woh,g_woh); cudaGetSymbolAddress(&wol,g_wol);
    cudaGetSymbolAddress(&w1h,g_w1h); cudaGetSymbolAddress(&w1l,g_w1l);
    cudaGetSymbolAddress(&w2h,g_w2h); cudaGetSymbolAddress(&w2l,g_w2l);

    k_split<<<4096,256>>>(x,(bf16*)xh,(bf16*)xl,(long)M0*IND);
    k_split<<<512,256>>>(Wr,(bf16*)wrh,(bf16*)wrl,(long)IND*DIM);
    k_split<<<2048,256>>>(Wp,(bf16*)wph,(bf16*)wpl,(long)NE*IND*DIM);
    k_split<<<2048,256>>>(Wqkv,(bf16*)wqh,(bf16*)wql,(long)NE*DEPTH*DIM*QD);
    k_split<<<1024,256>>>(Wo,(bf16*)woh,(bf16*)wol,(long)NE*DEPTH*DIM*DIM);
    k_split<<<1024,256>>>(W1,(bf16*)w1h,(bf16*)w1l,(long)NE*DEPTH*DIM*DIM);
    k_split<<<1024,256>>>(W2,(bf16*)w2h,(bf16*)w2l,(long)NE*DEPTH*DIM*DIM);

    const int gyM0=M0/128;                 // 64
    const int gyBS=(BS+127)/128;           // 65
    const int gyS=(SEQ+127)/128;           // 9

    wg_router<<<dim3(DIM/128,gyM0),256>>>(br);
    k_meanpool<<<BB,DIM>>>();
    k_router_head<<<1,32>>>(Wrf,brf);

    wg_expert<<<dim3(DIM/128,gyM0,NE),256>>>(bp);
    k_set_cls<<<dim3(BB,NE),DIM>>>(cls);

    for(int l=0;l<DEPTH;l++){
        k_ln<<<dim3(BS,NE),256>>>(ln1g+l*DIM,ln1b+l*DIM,(long)DEPTH*DIM,0);
        wg_qkv<<<dim3(QD/128,gyBS,NE),256>>>(bqkv,l);
        k_kt<<<dim3((KTP+31)/32,DHD/32,NSLICE),256>>>();
        wg_scores<<<dim3(gyS,gyS,NSLICE),256>>>();
        k_softmax<<<dim3(BB*NH*SEQ,NE),256>>>();
        wg_av<<<dim3(1,gyS,NSLICE),256>>>();
        wg_oproj<<<dim3(DIM/128,gyBS,NE),256>>>(bo,l);
        k_ln<<<dim3(BS,NE),256>>>(ln2g+l*DIM,ln2b+l*DIM,(long)DEPTH*DIM,0);
        wg_mlp1<<<dim3(DIM/128,gyBS,NE),256>>>(b1,l);
        wg_mlp2<<<dim3(DIM/128,gyBS,NE),256>>>(b2,l);
    }
    k_ln<<<dim3(BB,NE),256>>>(lnfg,lnfb,(long)DIM,1);
    k_head<<<NE*BB,320>>>(Wh,bh);
    k_combine<<<(out_size+255)/256,256>>>(out,out_size);
}

// round 17
// speedup vs baseline: 1.5721x; 1.0922x over previous
#include <cuda_runtime.h>
#include <cuda_bf16.h>
#include <mma.h>
#include <math.h>
#include <stdint.h>
#define DEV_INLINE __device__ __forceinline__
typedef __nv_bfloat16 bf16;
using namespace nvcuda;

constexpr int BB=8, NTOK=1024, IND=2048, DIM=512, NH=8, DHD=64, DEPTH=2, NE=4, NC=10;
constexpr int SEQ=NTOK+1, BS=BB*SEQ, M0=BB*NTOK, QD=3*DIM;
constexpr int KTP=1040, PLD=1056;
constexpr long TSZ=(long)BS*DIM, QKVSZ=(long)BS*QD, SS=(long)SEQ*SEQ;
constexpr int NSLICE=NE*BB*NH;

// fp32 state
__device__ float g_R[(size_t)M0*DIM];
__device__ float g_rmean[BB*DIM];
__device__ float g_gsoft[BB*NE];
__device__ float g_t[(size_t)NE*TSZ];
__device__ float g_sc[(size_t)NSLICE*SS];
__device__ float g_late[NE*BB*DIM];
__device__ float g_loge[NE*BB*NC];
// split-bf16 state
__device__ bf16 g_xh[(size_t)M0*IND], g_xl[(size_t)M0*IND];
__device__ bf16 g_hh[(size_t)NE*TSZ], g_hl[(size_t)NE*TSZ];
__device__ bf16 g_qvh[(size_t)NE*QKVSZ], g_qvl[(size_t)NE*QKVSZ];
__device__ bf16 g_kth[(size_t)NSLICE*DHD*KTP], g_ktl[(size_t)NSLICE*DHD*KTP];
__device__ bf16 g_ph[(size_t)NSLICE*SEQ*PLD], g_pl[(size_t)NSLICE*SEQ*PLD];
__device__ bf16 g_aoh[(size_t)NE*TSZ], g_aol[(size_t)NE*TSZ];
__device__ bf16 g_uh[(size_t)NE*TSZ], g_ul[(size_t)NE*TSZ];
// split weights (natural [K,N] layout)
__device__ bf16 g_wrh[(size_t)IND*DIM], g_wrl[(size_t)IND*DIM];
__device__ bf16 g_wph[(size_t)NE*IND*DIM], g_wpl[(size_t)NE*IND*DIM];
__device__ bf16 g_wqh[(size_t)NE*DEPTH*DIM*QD], g_wql[(size_t)NE*DEPTH*DIM*QD];
__device__ bf16 g_woh[(size_t)NE*DEPTH*DIM*DIM], g_wol[(size_t)NE*DEPTH*DIM*DIM];
__device__ bf16 g_w1h[(size_t)NE*DEPTH*DIM*DIM], g_w1l[(size_t)NE*DEPTH*DIM*DIM];
__device__ bf16 g_w2h[(size_t)NE*DEPTH*DIM*DIM], g_w2l[(size_t)NE*DEPTH*DIM*DIM];

DEV_INLINE float gelu_f(float x){return 0.5f*x*(1.f+tanhf(0.7978845608028654f*(x+0.044715f*x*x*x)));}
DEV_INLINE void split2(float v,bf16&h,bf16&l){h=__float2bfloat16(v);l=__float2bfloat16(v-__bfloat162float(h));}
DEV_INLINE float brsum(float v,float*sm){
    #pragma unroll
    for(int o=16;o;o>>=1)v+=__shfl_xor_sync(0xffffffffu,v,o);
    int t=threadIdx.x;if((t&31)==0)sm[t>>5]=v;__syncthreads();
    if(t<32){float z=(t<(int)(blockDim.x>>5))?sm[t]:0.f;
        #pragma unroll
        for(int o=4;o;o>>=1)z+=__shfl_xor_sync(0xffffffffu,z,o);
        if(t==0)sm[0]=z;}
    __syncthreads();float r=sm[0];__syncthreads();return r;}
DEV_INLINE float brmax(float v,float*sm){
    #pragma unroll
    for(int o=16;o;o>>=1)v=fmaxf(v,__shfl_xor_sync(0xffffffffu,v,o));
    int t=threadIdx.x;if((t&31)==0)sm[t>>5]=v;__syncthreads();
    if(t<32){float z=(t<(int)(blockDim.x>>5))?sm[t]:-1e30f;
        #pragma unroll
        for(int o=4;o;o>>=1)z=fmaxf(z,__shfl_xor_sync(0xffffffffu,z,o));
        if(t==0)sm[0]=z;}
    __syncthreads();float r=sm[0];__syncthreads();return r;}

// ======== wmma split-bf16 GEMM v3: pre-split inputs, BK=32, REGISTER PREFETCH ========
// C = act(alpha*(Ah+Al)[M,K]@(Bh+Bl)[K,N] + bias + res). res may alias C.
// K mult of 32; A rows readable to K; B rows guarded by Kb; B cols readable to Ncap.
template<int BN,int ACT,bool BIAS,bool RES,bool SHIFT,bool OUTSPLIT>
DEV_INLINE void tc2(const bf16* __restrict__ Ah,const bf16* __restrict__ Al,long lda,
                    const bf16* __restrict__ Bh,const bf16* __restrict__ Bl,long ldb,
                    const float* __restrict__ bias,const float* res,long ldres,
                    float* Cf,bf16* Ch,bf16* Cl,long ldc,
                    int M,int N,int K,int Kb,int Ncap,float alpha){
    constexpr int STRA=40, STRB=BN+8, NTW=BN/32, WCOL=BN/2;
    constexpr int UB=(32*BN/8+255)/256;           // B uint4 units per thread (2 for BN=128, 1 for 64)
    __shared__ __align__(32) bf16 sAh[128*STRA], sAl[128*STRA];
    __shared__ __align__(32) bf16 sBh[32*STRB], sBl[32*STRB];
    __shared__ __align__(32) float stg[8][256];
    const int tid=threadIdx.x, w=tid>>5, l=tid&31;
    const int wm=w&3, wn=w>>2;
    const int row0=blockIdx.y*128, col0=blockIdx.x*BN;
    const uint4 z4=make_uint4(0u,0u,0u,0u);

    wmma::fragment<wmma::accumulator,16,16,16,float> acc[2][NTW];
    #pragma unroll
    for(int mt=0;mt<2;mt++)
        #pragma unroll
        for(int nt=0;nt<NTW;nt++) wmma::fill_fragment(acc[mt][nt],0.f);

    uint4 rah[2],ral[2],rbh[UB],rbl[UB];
    auto fetch=[&](int kt){
        #pragma unroll
        for(int q=0;q<2;q++){
            int u=tid+q*256;
            int r=u>>2, cb=(u&3)*8;
            int gr=row0+r;
            uint4 vh=z4, vl=z4;
            if(gr<M){
                vh=*(const uint4*)(Ah+(long)gr*lda+kt+cb);
                vl=*(const uint4*)(Al+(long)gr*lda+kt+cb);
            }
            rah[q]=vh; ral[q]=vl;
        }
        #pragma unroll
        for(int q=0;q<UB;q++){
            int u=tid+q*256;
            int r=u/(BN/8), cb=(u%(BN/8))*8;
            int gk=kt+r;
            uint4 vh=z4, vl=z4;
            if(gk<Kb && col0+cb+8<=Ncap){
                vh=*(const uint4*)(Bh+(long)gk*ldb+col0+cb);
                vl=*(const uint4*)(Bl+(long)gk*ldb+col0+cb);
            }
            rbh[q]=vh; rbl[q]=vl;
        }
    };
    auto store=[&](){
        #pragma unroll
        for(int q=0;q<2;q++){
            int u=tid+q*256;
            int r=u>>2, cb=(u&3)*8;
            *(uint4*)(sAh+r*STRA+cb)=rah[q];
            *(uint4*)(sAl+r*STRA+cb)=ral[q];
        }
        #pragma unroll
        for(int q=0;q<UB;q++){
            int u=tid+q*256;
            int r=u/(BN/8), cb=(u%(BN/8))*8;
            *(uint4*)(sBh+r*STRB+cb)=rbh[q];
            *(uint4*)(sBl+r*STRB+cb)=rbl[q];
        }
    };

    const int T=K>>5;
    fetch(0); store();
    __syncthreads();
    for(int t=0;t<T;t++){
        if(t+1<T) fetch((t+1)<<5);
        #pragma unroll
        for(int ks=0;ks<2;ks++){
            wmma::fragment<wmma::matrix_b,16,16,16,bf16,wmma::row_major> fbh[NTW],fbl[NTW];
            #pragma unroll
            for(int nt=0;nt<NTW;nt++){
                wmma::load_matrix_sync(fbh[nt],&sBh[(ks*16)*STRB+wn*WCOL+nt*16],STRB);
                wmma::load_matrix_sync(fbl[nt],&sBl[(ks*16)*STRB+wn*WCOL+nt*16],STRB);
            }
            #pragma unroll
            for(int mt=0;mt<2;mt++){
                wmma::fragment<wmma::matrix_a,16,16,16,bf16,wmma::row_major> fah,fal;
                wmma::load_matrix_sync(fah,&sAh[(wm*32+mt*16)*STRA+ks*16],STRA);
                wmma::load_matrix_sync(fal,&sAl[(wm*32+mt*16)*STRA+ks*16],STRA);
                #pragma unroll
                for(int nt=0;nt<NTW;nt++){
                    wmma::mma_sync(acc[mt][nt],fah,fbh[nt],acc[mt][nt]);
                    wmma::mma_sync(acc[mt][nt],fah,fbl[nt],acc[mt][nt]);
                    wmma::mma_sync(acc[mt][nt],fal,fbh[nt],acc[mt][nt]);
                }
            }
        }
        __syncthreads();
        if(t+1<T){ store(); __syncthreads(); }
    }
    #pragma unroll
    for(int mt=0;mt<2;mt++){
        #pragma unroll
        for(int nt=0;nt<NTW;nt++){
            wmma::store_matrix_sync(stg[w],acc[mt][nt],16,wmma::mem_row_major);
            __syncwarp();
            int rr=l>>1, c0=(l&1)*8;
            int r=row0+wm*32+mt*16+rr;
            if(r<M){
                long orow=SHIFT?((long)r+r/1024+1):(long)r;
                #pragma unroll
                for(int j=0;j<8;j++){
                    int cc=col0+wn*WCOL+nt*16+c0+j;
                    if(cc>=N) continue;
                    float v=stg[w][rr*16+c0+j]*alpha;
                    if(BIAS)v+=bias[cc];
                    if(RES)v+=res[orow*ldres+cc];
                    if(ACT==1)v=fmaxf(v,0.f);else if(ACT==2)v=gelu_f(v);
                    if(OUTSPLIT){bf16 hh,ll;split2(v,hh,ll);Ch[orow*ldc+cc]=hh;Cl[orow*ldc+cc]=ll;}
                    else Cf[orow*ldc+cc]=v;
                }
            }
            __syncwarp();
        }
    }
}

// ---------------- GEMM wrappers ----------------
__global__ void __launch_bounds__(256) wg_router(const float*br){
    tc2<128,1,true,false,false,false>(g_xh,g_xl,IND,g_wrh,g_wrl,DIM,br,nullptr,0,
        g_R,nullptr,nullptr,DIM,M0,DIM,IND,IND,DIM,1.f);}
__global__ void __launch_bounds__(256) wg_expert(const float*bp){
    long e=blockIdx.z;
    tc2<128,1,true,false,true,false>(g_xh,g_xl,IND,g_wph+e*IND*DIM,g_wpl+e*IND*DIM,DIM,
        bp+e*DIM,nullptr,0,g_t+e*TSZ,nullptr,nullptr,DIM,M0,DIM,IND,IND,DIM,1.f);}
__global__ void __launch_bounds__(256) wg_qkv(const float*bqkv,int lyr){
    long e=blockIdx.z, we=e*DEPTH+lyr;
    tc2<128,0,true,false,false,true>(g_hh+e*TSZ,g_hl+e*TSZ,DIM,
        g_wqh+we*DIM*QD,g_wql+we*DIM*QD,QD,bqkv+we*QD,nullptr,0,
        nullptr,g_qvh+e*QKVSZ,g_qvl+e*QKVSZ,QD,BS,QD,DIM,DIM,QD,1.f);}
__global__ void __launch_bounds__(256) wg_scores(){
    long z=blockIdx.z;
    long e=z/(BB*NH), b=(z/NH)%BB, h=z%NH;
    const bf16* qh=g_qvh+e*QKVSZ+b*(long)SEQ*QD+h*DHD;
    const bf16* ql=g_qvl+e*QKVSZ+b*(long)SEQ*QD+h*DHD;
    tc2<128,0,false,false,false,false>(qh,ql,QD,
        g_kth+(size_t)z*DHD*KTP,g_ktl+(size_t)z*DHD*KTP,KTP,nullptr,nullptr,0,
        g_sc+(size_t)z*SS,nullptr,nullptr,SEQ,SEQ,SEQ,DHD,DHD,KTP,0.125f);}
__global__ void __launch_bounds__(256) wg_av(){
    long z=blockIdx.z;
    long e=z/(BB*NH), b=(z/NH)%BB, h=z%NH;
    tc2<64,0,false,false,false,true>(
        g_ph+(size_t)z*SEQ*PLD,g_pl+(size_t)z*SEQ*PLD,PLD,
        g_qvh+e*QKVSZ+b*(long)SEQ*QD+2*DIM+h*DHD,g_qvl+e*QKVSZ+b*(long)SEQ*QD+2*DIM+h*DHD,QD,
        nullptr,nullptr,0,
        nullptr,g_aoh+e*TSZ+b*(long)SEQ*DIM+h*DHD,g_aol+e*TSZ+b*(long)SEQ*DIM+h*DHD,DIM,
        SEQ,DHD,PLD,SEQ,DHD,1.f);}
__global__ void __launch_bounds__(256) wg_oproj(const float*bo,int lyr){
    long e=blockIdx.z, we=e*DEPTH+lyr;
    tc2<128,0,true,true,false,false>(g_aoh+e*TSZ,g_aol+e*TSZ,DIM,
        g_woh+we*DIM*DIM,g_wol+we*DIM*DIM,DIM,bo+we*DIM,g_t+e*TSZ,DIM,
        g_t+e*TSZ,nullptr,nullptr,DIM,BS,DIM,DIM,DIM,DIM,1.f);}
__global__ void __launch_bounds__(256) wg_mlp1(const float*b1,int lyr){
    long e=blockIdx.z, we=e*DEPTH+lyr;
    tc2<128,2,true,false,false,true>(g_hh+e*TSZ,g_hl+e*TSZ,DIM,
        g_w1h+we*DIM*DIM,g_w1l+we*DIM*DIM,DIM,b1+we*DIM,nullptr,0,
        nullptr,g_uh+e*TSZ,g_ul+e*TSZ,DIM,BS,DIM,DIM,DIM,DIM,1.f);}
__global__ void __launch_bounds__(256) wg_mlp2(const float*b2,int lyr){
    long e=blockIdx.z, we=e*DEPTH+lyr;
    tc2<128,0,true,true,false,false>(g_uh+e*TSZ,g_ul+e*TSZ,DIM,
        g_w2h+we*DIM*DIM,g_w2l+we*DIM*DIM,DIM,b2+we*DIM,g_t+e*TSZ,DIM,
        g_t+e*TSZ,nullptr,nullptr,DIM,BS,DIM,DIM,DIM,DIM,1.f);}

// ---------------- prep / elementwise ----------------
__global__ void __launch_bounds__(256) k_split(const float* __restrict__ s,bf16* __restrict__ h,
                                               bf16* __restrict__ l,long n){
    for(long i=blockIdx.x*256L+threadIdx.x;i<n;i+=(long)gridDim.x*256L){
        float v=s[i];bf16 hh=__float2bfloat16(v);h[i]=hh;l[i]=__float2bfloat16(v-__bfloat162float(hh));}}
__global__ void __launch_bounds__(256) k_kt(){
    __shared__ bf16 th[32][33], tl[32][33];
    long z=blockIdx.z;
    long e=z/(BB*NH), b=(z/NH)%BB, h=z%NH;
    const bf16* sh=g_qvh+e*QKVSZ+b*(long)SEQ*QD+DIM+h*DHD;
    const bf16* sl=g_qvl+e*QKVSZ+b*(long)SEQ*QD+DIM+h*DHD;
    int s0=blockIdx.x*32, d0=blockIdx.y*32;
    int tx=threadIdx.x&31, ty=threadIdx.x>>5;
    for(int i=ty;i<32;i+=8){
        int s=s0+i;
        th[i][tx]=(s<SEQ)?sh[(long)s*QD+d0+tx]:bf16(0.f);
        tl[i][tx]=(s<SEQ)?sl[(long)s*QD+d0+tx]:bf16(0.f);
    }
    __syncthreads();
    bf16* dh=g_kth+(size_t)z*DHD*KTP;
    bf16* dl=g_ktl+(size_t)z*DHD*KTP;
    for(int i=ty;i<32;i+=8){
        int d=d0+i, s=s0+tx;
        if(s<KTP){ dh[(long)d*KTP+s]=th[tx][i]; dl[(long)d*KTP+s]=tl[tx][i]; }
    }
}
__global__ void __launch_bounds__(512) k_set_cls(const float*cls){
    int b=blockIdx.x,e=blockIdx.y;
    g_t[(size_t)e*TSZ+(size_t)b*SEQ*DIM+threadIdx.x]=cls[e*DIM+threadIdx.x];}
__global__ void __launch_bounds__(256) k_ln(const float*g,const float*bb,long gE,int fin){
    __shared__ float sm[8];
    int e=blockIdx.y;const float*xp;long ob;
    if(fin==0){long row=blockIdx.x;xp=g_t+(long)e*TSZ+row*DIM;ob=(long)e*TSZ+row*DIM;}
    else{int b=blockIdx.x;xp=g_t+(long)e*TSZ+(long)b*SEQ*DIM;ob=((long)e*BB+b)*DIM;}
    const float*gp=g+e*gE;const float*bp=bb+e*gE;
    int t=threadIdx.x;
    float x0=xp[t],x1=xp[t+256];
    float s=brsum(x0+x1,sm), sq=brsum(x0*x0+x1*x1,sm);
    float m=s*(1.f/DIM), v=sq*(1.f/DIM)-m*m, inv=rsqrtf(v+1e-5f);
    float y0=(x0-m)*inv*gp[t]+bp[t], y1=(x1-m)*inv*gp[t+256]+bp[t+256];
    if(fin==0){bf16 hh,ll;
        split2(y0,hh,ll);g_hh[ob+t]=hh;g_hl[ob+t]=ll;
        split2(y1,hh,ll);g_hh[ob+t+256]=hh;g_hl[ob+t+256]=ll;
    }else{g_late[ob+t]=y0;g_late[ob+t+256]=y1;}}
__global__ void __launch_bounds__(256) k_softmax(){
    __shared__ float sm[8];
    int e=blockIdx.y;long rowIn=blockIdx.x;
    const float*p=g_sc+(size_t)e*((long)BB*NH*SS)+rowIn*SEQ;
    long z=(long)e*(BB*NH)+rowIn/SEQ, q=rowIn%SEQ;
    bf16*oh=g_ph+(z*(long)SEQ+q)*PLD;
    bf16*ol=g_pl+(z*(long)SEQ+q)*PLD;
    int t=threadIdx.x;float v[5],mx=-1e30f;
    #pragma unroll
    for(int i=0;i<5;i++){int idx=t+i*256;v[i]=(idx<SEQ)?p[idx]:-1e30f;mx=fmaxf(mx,v[i]);}
    mx=brmax(mx,sm);
    float s=0.f;
    #pragma unroll
    for(int i=0;i<5;i++){int idx=t+i*256;if(idx<SEQ){v[i]=__expf(v[i]-mx);s+=v[i];}else v[i]=0.f;}
    s=brsum(s,sm);float inv=1.f/s;
    #pragma unroll
    for(int i=0;i<5;i++){
        int idx=t+i*256;
        if(idx<SEQ){bf16 hh,ll;split2(v[i]*inv,hh,ll);oh[idx]=hh;ol[idx]=ll;}
        else if(idx<PLD){oh[idx]=bf16(0.f);ol[idx]=bf16(0.f);}
    }}
__global__ void __launch_bounds__(512) k_meanpool(){
    int b=blockIdx.x,d=threadIdx.x;
    const float*p=g_R+(long)b*NTOK*DIM+d;float s=0.f;
    for(int n=0;n<NTOK;n++)s+=p[(long)n*DIM];
    g_rmean[b*DIM+d]=s*(1.f/NTOK);}
__global__ void __launch_bounds__(32) k_router_head(const float*Wrf,const float*brf){
    __shared__ float lg[BB][NE];
    int t=threadIdx.x;
    if(t<BB*NE){int b=t/NE,e=t%NE;float s=brf[e];
        for(int d=0;d<DIM;d++)s+=g_rmean[b*DIM+d]*Wrf[d*NE+e];
        lg[b][e]=s;}
    __syncthreads();
    if(t<BB){float mx=-1e30f;
        for(int e=0;e<NE;e++)mx=fmaxf(mx,lg[t][e]);
        float ex[NE],sum=0.f;
        for(int e=0;e<NE;e++){ex[e]=__expf(lg[t][e]-mx);sum+=ex[e];}
        for(int e=0;e<NE;e++)g_gsoft[t*NE+e]=ex[e]/sum;}}
__global__ void __launch_bounds__(320) k_head(const float*Wh,const float*bh){
    int eb=blockIdx.x,e=eb/BB;
    int w=threadIdx.x>>5,lane=threadIdx.x&31;
    const float*lat=g_late+(long)eb*DIM;const float*wp=Wh+(long)e*DIM*NC;
    float s=0.f;
    for(int d=lane;d<DIM;d+=32)s+=lat[d]*wp[d*NC+w];
    #pragma unroll
    for(int o=16;o;o>>=1)s+=__shfl_xor_sync(0xffffffffu,s,o);
    if(lane==0)g_loge[eb*NC+w]=s+bh[e*NC+w];}
__global__ void __launch_bounds__(256) k_combine(float*out,int n){
    int idx=blockIdx.x*256+threadIdx.x;if(idx>=n)return;
    if(idx<BB*DIM){int b=idx/DIM,d=idx%DIM;float s=0.f;
        for(int e=0;e<NE;e++)s+=g_gsoft[b*NE+e]*g_late[(e*BB+b)*DIM+d];out[idx]=s;}
    else if(idx<BB*DIM+BB*NC){int i=idx-BB*DIM,b=i/NC,c=i%NC;float s=0.f;
        for(int e=0;e<NE;e++)s+=g_gsoft[b*NE+e]*g_loge[(e*BB+b)*NC+c];out[idx]=s;}
    else if(idx<BB*DIM+BB*NC+BB*NE)out[idx]=g_gsoft[idx-BB*DIM-BB*NC];
    else out[idx]=0.f;}

extern "C" void kernel_launch(void* const* d_in,const int* in_sizes,int n_in,void* d_out,int out_size){
    const float*x=(const float*)d_in[0],*Wr=(const float*)d_in[1],*br=(const float*)d_in[2];
    const float*Wrf=(const float*)d_in[3],*brf=(const float*)d_in[4];
    const float*Wp=(const float*)d_in[5],*bp=(const float*)d_in[6],*cls=(const float*)d_in[7];
    const float*ln1g=(const float*)d_in[8],*ln1b=(const float*)d_in[9];
    const float*Wqkv=(const float*)d_in[10],*bqkv=(const float*)d_in[11];
    const float*Wo=(const float*)d_in[12],*bo=(const float*)d_in[13];
    const float*ln2g=(const float*)d_in[14],*ln2b=(const float*)d_in[15];
    const float*W1=(const float*)d_in[16],*b1=(const float*)d_in[17];
    const float*W2=(const float*)d_in[18],*b2=(const float*)d_in[19];
    const float*lnfg=(const float*)d_in[20],*lnfb=(const float*)d_in[21];
    const float*Wh=(const float*)d_in[22],*bh=(const float*)d_in[23];
    float*out=(float*)d_out;

    void *xh,*xl,*wrh,*wrl,*wph,*wpl,*wqh,*wql,*woh,*wol,*w1h,*w1l,*w2h,*w2l;
    cudaGetSymbolAddress(&xh,g_xh);   cudaGetSymbolAddress(&xl,g_xl);
    cudaGetSymbolAddress(&wrh,g_wrh); cudaGetSymbolAddress(&wrl,g_wrl);
    cudaGetSymbolAddress(&wph,g_wph); cudaGetSymbolAddress(&wpl,g_wpl);
    cudaGetSymbolAddress(&wqh,g_wqh); cudaGetSymbolAddress(&wql,g_wql);
    cudaGetSymbolAddress(&woh,g_woh); cudaGetSymbolAddress(&wol,g_wol);
    cudaGetSymbolAddress(&w1h,g_w1h); cudaGetSymbolAddress(&w1l,g_w1l);
    cudaGetSymbolAddress(&w2h,g_w2h); cudaGetSymbolAddress(&w2l,g_w2l);

    k_split<<<4096,256>>>(x,(bf16*)xh,(bf16*)xl,(long)M0*IND);
    k_split<<<512,256>>>(Wr,(bf16*)wrh,(bf16*)wrl,(long)IND*DIM);
    k_split<<<2048,256>>>(Wp,(bf16*)wph,(bf16*)wpl,(long)NE*IND*DIM);
    k_split<<<2048,256>>>(Wqkv,(bf16*)wqh,(bf16*)wql,(long)NE*DEPTH*DIM*QD);
    k_split<<<1024,256>>>(Wo,(bf16*)woh,(bf16*)wol,(long)NE*DEPTH*DIM*DIM);
    k_split<<<1024,256>>>(W1,(bf16*)w1h,(bf16*)w1l,(long)NE*DEPTH*DIM*DIM);
    k_split<<<1024,256>>>(W2,(bf16*)w2h,(bf16*)w2l,(long)NE*DEPTH*DIM*DIM);

    const int gyM0=M0/128;                 // 64
    const int gyBS=(BS+127)/128;           // 65
    const int gyS=(SEQ+127)/128;           // 9

    wg_router<<<dim3(DIM/128,gyM0),256>>>(br);
    k_meanpool<<<BB,DIM>>>();
    k_router_head<<<1,32>>>(Wrf,brf);

    wg_expert<<<dim3(DIM/128,gyM0,NE),256>>>(bp);
    k_set_cls<<<dim3(BB,NE),DIM>>>(cls);

    for(int l=0;l<DEPTH;l++){
        k_ln<<<dim3(BS,NE),256>>>(ln1g+l*DIM,ln1b+l*DIM,(long)DEPTH*DIM,0);
        wg_qkv<<<dim3(QD/128,gyBS,NE),256>>>(bqkv,l);
        k_kt<<<dim3((KTP+31)/32,DHD/32,NSLICE),256>>>();
        wg_scores<<<dim3(gyS,gyS,NSLICE),256>>>();
        k_softmax<<<dim3(BB*NH*SEQ,NE),256>>>();
        wg_av<<<dim3(1,gyS,NSLICE),256>>>();
        wg_oproj<<<dim3(DIM/128,gyBS,NE),256>>>(bo,l);
        k_ln<<<dim3(BS,NE),256>>>(ln2g+l*DIM,ln2b+l*DIM,(long)DEPTH*DIM,0);
        wg_mlp1<<<dim3(DIM/128,gyBS,NE),256>>>(b1,l);
        wg_mlp2<<<dim3(DIM/128,gyBS,NE),256>>>(b2,l);
    }
    k_ln<<<dim3(BB,NE),256>>>(lnfg,lnfb,(long)DIM,1);
    k_head<<<NE*BB,320>>>(Wh,bh);
    k_combine<<<(out_size+255)/256,256>>>(out,out_size);
}